// round 1
// baseline (speedup 1.0000x reference)
#include <cuda_runtime.h>
#include <math.h>

// Problem constants (fixed-shape problem)
#define FDIM 128
#define DDEG 16
#define KH   2048   // K*H
#define ODIM 256
#define JS   16     // j-split for the M precompute
#define JCH  (KH/JS) // 128

// Scratch (no device allocation allowed -> __device__ globals)
__device__ float g_Mpart[JS][2][FDIM][ODIM];  // 4 MB partials
__device__ float g_M[2][FDIM][ODIM];          // [0]=Ms (pairs with x), [1]=Mn (pairs with neigh_mean)

// ---------------------------------------------------------------------------
// Kernel A: partial M[m][f][o] = sum_{j in chunk} Rflat[f][j] * W_m[o][j]
//   Rflat[f][j] = R[j>>8][f][j&255]
// grid: (f_tiles=2, o_tiles=4, 2*JS), block 256, 4x4 register tiles.
// ---------------------------------------------------------------------------
__global__ void __launch_bounds__(256)
kA(const float* __restrict__ R, const float* __restrict__ Ws,
   const float* __restrict__ Wn)
{
    __shared__ float sA[32][68];  // [jj][f]  (64 f + pad)
    __shared__ float sB[32][68];  // [jj][o]

    const int ft = blockIdx.x;            // 0..1
    const int ot = blockIdx.y;            // 0..3
    const int mz = blockIdx.z;            // 0..2*JS-1
    const int m  = mz / JS;
    const int jc = mz % JS;
    const float* __restrict__ W = m ? Wn : Ws;

    const int f0 = ft * 64, o0 = ot * 64;
    const int jbase = jc * JCH;
    const int kk = jbase >> 8;            // constant within 128-j chunk
    const int hb = jbase & 255;

    const int tid = threadIdx.x;
    const int tx = tid & 15;              // o quad
    const int ty = tid >> 4;              // f quad

    float acc[4][4];
    #pragma unroll
    for (int i = 0; i < 4; i++)
        #pragma unroll
        for (int j = 0; j < 4; j++) acc[i][j] = 0.f;

    for (int jt = 0; jt < JCH; jt += 32) {
        // load Rflat tile (64f x 32j), transposed into sA[jj][f]
        #pragma unroll
        for (int r = 0; r < 2; r++) {
            int li = tid + r * 256;           // float4 index, 0..511
            int f_l = li >> 3;
            int jj  = (li & 7) * 4;
            float4 a4 = *(const float4*)(R + (size_t)kk * (FDIM * 256)
                                           + (size_t)(f0 + f_l) * 256 + hb + jt + jj);
            sA[jj + 0][f_l] = a4.x; sA[jj + 1][f_l] = a4.y;
            sA[jj + 2][f_l] = a4.z; sA[jj + 3][f_l] = a4.w;
        }
        // load W tile (64o x 32j), transposed into sB[jj][o]
        #pragma unroll
        for (int r = 0; r < 2; r++) {
            int li = tid + r * 256;
            int o_l = li >> 3;
            int jj  = (li & 7) * 4;
            float4 b4 = *(const float4*)(W + (size_t)(o0 + o_l) * KH + jbase + jt + jj);
            sB[jj + 0][o_l] = b4.x; sB[jj + 1][o_l] = b4.y;
            sB[jj + 2][o_l] = b4.z; sB[jj + 3][o_l] = b4.w;
        }
        __syncthreads();
        #pragma unroll
        for (int jj = 0; jj < 32; jj++) {
            float4 a4 = *(const float4*)&sA[jj][ty * 4];
            float4 b4 = *(const float4*)&sB[jj][tx * 4];
            float a[4] = {a4.x, a4.y, a4.z, a4.w};
            float b[4] = {b4.x, b4.y, b4.z, b4.w};
            #pragma unroll
            for (int i = 0; i < 4; i++)
                #pragma unroll
                for (int j = 0; j < 4; j++)
                    acc[i][j] += a[i] * b[j];
        }
        __syncthreads();
    }

    float* outp = &g_Mpart[jc][m][0][0];
    #pragma unroll
    for (int i = 0; i < 4; i++) {
        float4 v = make_float4(acc[i][0], acc[i][1], acc[i][2], acc[i][3]);
        *(float4*)(outp + (size_t)(f0 + ty * 4 + i) * ODIM + o0 + tx * 4) = v;
    }
}

// Deterministic reduction of the JS partials.
__global__ void __launch_bounds__(256)
kReduce()
{
    int i = blockIdx.x * 256 + threadIdx.x;   // 0..65535
    const float* p = (const float*)g_Mpart;
    float s = 0.f;
    #pragma unroll
    for (int q = 0; q < JS; q++) s += p[(size_t)q * 2 * FDIM * ODIM + i];
    ((float*)g_M)[i] = s;
}

// ---------------------------------------------------------------------------
// Kernel B: per block = 64 nodes x all 256 outputs.
//   Phase 0: gather-mean 16 neighbors into nmT (transposed smem), load self xsT.
//   Phase 1: out = xs @ Ms + nm @ Mn  (8n x 8o register tiles per thread).
//   Phase 2: + bias, ELU, store.
// ---------------------------------------------------------------------------
__global__ void __launch_bounds__(256, 2)
kB(const float* __restrict__ x, const int* __restrict__ nbr,
   const float* __restrict__ bias, float* __restrict__ out, int N)
{
    extern __shared__ float sm[];
    float* xsT = sm;                       // [128][68] transposed self feats
    float* nmT = sm + 128 * 68;            // [128][68] transposed neighbor mean
    float* Msm = sm + 2 * 128 * 68;        // [2][16][256] M chunk
    int*   sIdx = (int*)(Msm + 2 * 16 * 256); // [64][16]

    const int tid = threadIdx.x;
    const int nb  = blockIdx.x * 64;

    // neighbor indices
    #pragma unroll
    for (int r = 0; r < 4; r++) {
        int li = tid + r * 256;            // 0..1023
        int n_l = li >> 4;
        sIdx[li] = (nb + n_l < N) ? nbr[(size_t)(nb + n_l) * DDEG + (li & 15)] : 0;
    }
    __syncthreads();

    // gather-mean (each thread: one node, one 32-float slice)
    {
        const int n_l = tid & 63;
        const int fc  = (tid >> 6) * 32;
        const bool valid = (nb + n_l) < N;
        float4 a[8];
        #pragma unroll
        for (int q = 0; q < 8; q++) a[q] = make_float4(0.f, 0.f, 0.f, 0.f);
        if (valid) {
            #pragma unroll 4
            for (int d = 0; d < DDEG; d++) {
                const float4* p = (const float4*)(x + (size_t)sIdx[n_l * DDEG + d] * FDIM + fc);
                #pragma unroll
                for (int q = 0; q < 8; q++) {
                    float4 v = p[q];
                    a[q].x += v.x; a[q].y += v.y; a[q].z += v.z; a[q].w += v.w;
                }
            }
        }
        #pragma unroll
        for (int q = 0; q < 8; q++) {
            nmT[(fc + q * 4 + 0) * 68 + n_l] = a[q].x * 0.0625f;
            nmT[(fc + q * 4 + 1) * 68 + n_l] = a[q].y * 0.0625f;
            nmT[(fc + q * 4 + 2) * 68 + n_l] = a[q].z * 0.0625f;
            nmT[(fc + q * 4 + 3) * 68 + n_l] = a[q].w * 0.0625f;
        }
        // self rows -> transposed smem
        #pragma unroll
        for (int r = 0; r < 8; r++) {
            int li4 = tid + r * 256;       // float4 index over [64][32]
            int n2  = li4 >> 5;
            int f4  = li4 & 31;
            float4 v = make_float4(0.f, 0.f, 0.f, 0.f);
            if (nb + n2 < N) v = *(const float4*)(x + (size_t)(nb + n2) * FDIM + f4 * 4);
            xsT[(f4 * 4 + 0) * 68 + n2] = v.x;
            xsT[(f4 * 4 + 1) * 68 + n2] = v.y;
            xsT[(f4 * 4 + 2) * 68 + n2] = v.z;
            xsT[(f4 * 4 + 3) * 68 + n2] = v.w;
        }
    }

    // GEMM: acc[n_sub=8][o_sub=8]; o = g*128 + tx*4 + j  (g = j>>2)
    float acc[8][8];
    #pragma unroll
    for (int i = 0; i < 8; i++)
        #pragma unroll
        for (int j = 0; j < 8; j++) acc[i][j] = 0.f;

    const int tx = tid & 31;
    const int ty = tid >> 5;

    for (int fb = 0; fb < FDIM; fb += 16) {
        __syncthreads();
        // stage M chunk: [2][16][256]
        #pragma unroll
        for (int r = 0; r < 8; r++) {
            int li4 = tid + r * 256;       // 0..2047 float4
            int m   = li4 >> 10;
            int rem = li4 & 1023;
            int ff  = rem >> 6;
            int o4  = rem & 63;
            float4 v = *(const float4*)(&g_M[m][fb + ff][o4 * 4]);
            *(float4*)&Msm[((size_t)m * 16 + ff) * 256 + o4 * 4] = v;
        }
        __syncthreads();
        #pragma unroll
        for (int ff = 0; ff < 16; ff++) {
            const float* xrow = &xsT[(fb + ff) * 68];
            const float* nrow = &nmT[(fb + ff) * 68];
            float4 ax0 = *(const float4*)(xrow + ty * 8);
            float4 ax1 = *(const float4*)(xrow + ty * 8 + 4);
            float4 an0 = *(const float4*)(nrow + ty * 8);
            float4 an1 = *(const float4*)(nrow + ty * 8 + 4);
            const float* ms = &Msm[(size_t)ff * 256];
            const float* mn = &Msm[(size_t)(16 + ff) * 256];
            float4 bs0 = *(const float4*)(ms + tx * 4);
            float4 bs1 = *(const float4*)(ms + 128 + tx * 4);
            float4 bn0 = *(const float4*)(mn + tx * 4);
            float4 bn1 = *(const float4*)(mn + 128 + tx * 4);
            float ax[8] = {ax0.x, ax0.y, ax0.z, ax0.w, ax1.x, ax1.y, ax1.z, ax1.w};
            float an[8] = {an0.x, an0.y, an0.z, an0.w, an1.x, an1.y, an1.z, an1.w};
            float bs[8] = {bs0.x, bs0.y, bs0.z, bs0.w, bs1.x, bs1.y, bs1.z, bs1.w};
            float bn[8] = {bn0.x, bn0.y, bn0.z, bn0.w, bn1.x, bn1.y, bn1.z, bn1.w};
            #pragma unroll
            for (int i = 0; i < 8; i++)
                #pragma unroll
                for (int j = 0; j < 8; j++)
                    acc[i][j] += ax[i] * bs[j] + an[i] * bn[j];
        }
    }

    // epilogue: +bias, ELU, store
    float4 b0 = *(const float4*)(bias + tx * 4);
    float4 b1 = *(const float4*)(bias + 128 + tx * 4);
    float bb[8] = {b0.x, b0.y, b0.z, b0.w, b1.x, b1.y, b1.z, b1.w};
    #pragma unroll
    for (int i = 0; i < 8; i++) {
        int n = nb + ty * 8 + i;
        if (n < N) {
            float v[8];
            #pragma unroll
            for (int j = 0; j < 8; j++) {
                float t = acc[i][j] + bb[j];
                v[j] = (t > 0.f) ? t : expm1f(t);
            }
            *(float4*)(out + (size_t)n * ODIM + tx * 4)       = make_float4(v[0], v[1], v[2], v[3]);
            *(float4*)(out + (size_t)n * ODIM + 128 + tx * 4) = make_float4(v[4], v[5], v[6], v[7]);
        }
    }
}

// ---------------------------------------------------------------------------
extern "C" void kernel_launch(void* const* d_in, const int* in_sizes, int n_in,
                              void* d_out, int out_size)
{
    const float* x    = (const float*)d_in[0];   // [N,128]
    const int*   nbr  = (const int*)  d_in[1];   // [N,16]
    const float* R    = (const float*)d_in[2];   // [8,128,256]
    const float* Ws   = (const float*)d_in[3];   // [256,2048]
    const float* Wn   = (const float*)d_in[4];   // [256,2048]
    const float* bias = (const float*)d_in[5];   // [256]
    const int N = in_sizes[0] / FDIM;

    const int smemB = (2 * 128 * 68 + 2 * 16 * 256) * 4 + 64 * 16 * 4; // 106496 B
    cudaFuncSetAttribute(kB, cudaFuncAttributeMaxDynamicSharedMemorySize, smemB);

    kA<<<dim3(2, 4, 2 * JS), 256>>>(R, Ws, Wn);
    kReduce<<<(2 * FDIM * ODIM) / 256, 256>>>();
    kB<<<(N + 63) / 64, 256, smemB>>>(x, nbr, bias, (float*)d_out, N);
}

// round 3
// speedup vs baseline: 1.5773x; 1.5773x over previous
#include <cuda_runtime.h>
#include <cuda_bf16.h>
#include <math.h>
#include <stdint.h>

// ---------------------------------------------------------------------------
#define FDIM 128
#define DDEG 16
#define KH   2048
#define ODIM 256
#define JS   16
#define JCH  (KH/JS)

// Scratch (device globals; no allocation allowed)
__device__ float g_Mpart[JS][2][FDIM][ODIM];                 // 4 MB partials
__device__ __align__(16) __nv_bfloat16 g_Bhi[ODIM * 256];    // B[o][k] hi
__device__ __align__(16) __nv_bfloat16 g_Blo[ODIM * 256];    // B[o][k] lo

// ---------------------------------------------------------------------------
// Kernel A: partial M[m][f][o] over a 128-wide j chunk (fp32, tiny: ~14us)
// ---------------------------------------------------------------------------
__global__ void __launch_bounds__(256)
kA(const float* __restrict__ R, const float* __restrict__ Ws,
   const float* __restrict__ Wn)
{
    __shared__ float sA[32][68];
    __shared__ float sB[32][68];

    const int ft = blockIdx.x, ot = blockIdx.y, mz = blockIdx.z;
    const int m = mz / JS, jc = mz % JS;
    const float* __restrict__ W = m ? Wn : Ws;
    const int f0 = ft * 64, o0 = ot * 64;
    const int jbase = jc * JCH;
    const int kk = jbase >> 8, hb = jbase & 255;
    const int tid = threadIdx.x, tx = tid & 15, ty = tid >> 4;

    float acc[4][4];
    #pragma unroll
    for (int i = 0; i < 4; i++)
        #pragma unroll
        for (int j = 0; j < 4; j++) acc[i][j] = 0.f;

    for (int jt = 0; jt < JCH; jt += 32) {
        #pragma unroll
        for (int r = 0; r < 2; r++) {
            int li = tid + r * 256;
            int f_l = li >> 3, jj = (li & 7) * 4;
            float4 a4 = *(const float4*)(R + (size_t)kk * (FDIM * 256)
                                           + (size_t)(f0 + f_l) * 256 + hb + jt + jj);
            sA[jj + 0][f_l] = a4.x; sA[jj + 1][f_l] = a4.y;
            sA[jj + 2][f_l] = a4.z; sA[jj + 3][f_l] = a4.w;
        }
        #pragma unroll
        for (int r = 0; r < 2; r++) {
            int li = tid + r * 256;
            int o_l = li >> 3, jj = (li & 7) * 4;
            float4 b4 = *(const float4*)(W + (size_t)(o0 + o_l) * KH + jbase + jt + jj);
            sB[jj + 0][o_l] = b4.x; sB[jj + 1][o_l] = b4.y;
            sB[jj + 2][o_l] = b4.z; sB[jj + 3][o_l] = b4.w;
        }
        __syncthreads();
        #pragma unroll
        for (int jj = 0; jj < 32; jj++) {
            float4 a4 = *(const float4*)&sA[jj][ty * 4];
            float4 b4 = *(const float4*)&sB[jj][tx * 4];
            float a[4] = {a4.x, a4.y, a4.z, a4.w};
            float b[4] = {b4.x, b4.y, b4.z, b4.w};
            #pragma unroll
            for (int i = 0; i < 4; i++)
                #pragma unroll
                for (int j = 0; j < 4; j++) acc[i][j] += a[i] * b[j];
        }
        __syncthreads();
    }
    float* outp = &g_Mpart[jc][m][0][0];
    #pragma unroll
    for (int i = 0; i < 4; i++) {
        float4 v = make_float4(acc[i][0], acc[i][1], acc[i][2], acc[i][3]);
        *(float4*)(outp + (size_t)(f0 + ty * 4 + i) * ODIM + o0 + tx * 4) = v;
    }
}

// Reduce partials, split to bf16 hi/lo, transpose to B[o][k], k = m*128+f.
__global__ void __launch_bounds__(256)
kReduce()
{
    int i = blockIdx.x * 256 + threadIdx.x;  // [m][f][o]
    const float* p = (const float*)g_Mpart;
    float s = 0.f;
    #pragma unroll
    for (int q = 0; q < JS; q++) s += p[(size_t)q * 2 * FDIM * ODIM + i];
    int m = i >> 15, f = (i >> 8) & 127, o = i & 255;
    int k = m * 128 + f;
    __nv_bfloat16 h = __float2bfloat16_rn(s);
    float r = s - __bfloat162float(h);
    g_Bhi[o * 256 + k] = h;
    g_Blo[o * 256 + k] = __float2bfloat16_rn(r);
}

// ---------------------------------------------------------------------------
// kB_mma: per CTA 128 nodes x 256 outs via mma.sync m16n8k16 bf16 (3-pass split)
// ---------------------------------------------------------------------------
#define AS 264   // A smem row stride (bf16), k-pair frag loads conflict-free
#define BS 72    // B smem row stride (bf16)

#define SM_AH 0
#define SM_AL (SM_AH + 128 * AS * 2)
#define SM_BH (SM_AL + 128 * AS * 2)
#define SM_BL (SM_BH + 128 * BS * 2)
#define SM_IX (SM_BL + 128 * BS * 2)
#define SM_TOT (SM_IX + 128 * 17 * 4)      // 180,736 B

__device__ __forceinline__ void mma_bf16(float* c, const uint32_t* a,
                                         uint32_t b0, uint32_t b1) {
    asm volatile(
        "mma.sync.aligned.m16n8k16.row.col.f32.bf16.bf16.f32 "
        "{%0,%1,%2,%3}, {%4,%5,%6,%7}, {%8,%9}, {%0,%1,%2,%3};"
        : "+f"(c[0]), "+f"(c[1]), "+f"(c[2]), "+f"(c[3])
        : "r"(a[0]), "r"(a[1]), "r"(a[2]), "r"(a[3]), "r"(b0), "r"(b1));
}

__device__ __forceinline__ void put_hl(__nv_bfloat16* Ah, __nv_bfloat16* Al,
                                       int off, float v0, float v1) {
    __nv_bfloat16 h0 = __float2bfloat16_rn(v0), h1 = __float2bfloat16_rn(v1);
    float l0 = v0 - __bfloat162float(h0), l1 = v1 - __bfloat162float(h1);
    __nv_bfloat162 hp; hp.x = h0; hp.y = h1;
    __nv_bfloat162 lp; lp.x = __float2bfloat16_rn(l0); lp.y = __float2bfloat16_rn(l1);
    *(__nv_bfloat162*)(Ah + off) = hp;
    *(__nv_bfloat162*)(Al + off) = lp;
}

__global__ void __launch_bounds__(256, 1)
kB_mma(const float* __restrict__ x, const int* __restrict__ nbr,
       const float* __restrict__ bias, float* __restrict__ out, int N)
{
    extern __shared__ char smem[];
    __nv_bfloat16* Ah = (__nv_bfloat16*)(smem + SM_AH);
    __nv_bfloat16* Al = (__nv_bfloat16*)(smem + SM_AL);
    __nv_bfloat16* Bh = (__nv_bfloat16*)(smem + SM_BH);
    __nv_bfloat16* Bl = (__nv_bfloat16*)(smem + SM_BL);
    int* sIdx = (int*)(smem + SM_IX);

    const int tid = threadIdx.x;
    const int nb = blockIdx.x * 128;

    // --- neighbor indices (stride 17 to dodge bank conflicts) ---
    #pragma unroll
    for (int r = 0; r < 8; r++) {
        int li = tid + r * 256;               // 0..2047
        int nl = li >> 4, d = li & 15;
        int src = nb + nl; if (src >= N) src = N - 1;
        sIdx[nl * 17 + d] = nbr[(size_t)src * DDEG + d];
    }
    __syncthreads();

    // --- gather-mean + self -> split-bf16 A in smem ---
    {
        const int node = tid & 127;
        const int q = tid >> 7;               // feature half
        int nsrc = nb + node; if (nsrc >= N) nsrc = N - 1;
        const int* myidx = &sIdx[node * 17];

        #pragma unroll
        for (int blk = 0; blk < 2; blk++) {
            const int fb = q * 64 + blk * 32;
            // neighbor mean over 32 feats
            float4 a[8];
            #pragma unroll
            for (int j = 0; j < 8; j++) a[j] = make_float4(0.f, 0.f, 0.f, 0.f);
            #pragma unroll 2
            for (int d = 0; d < DDEG; d++) {
                const float4* p = (const float4*)(x + (size_t)myidx[d] * FDIM + fb);
                #pragma unroll
                for (int j = 0; j < 8; j++) {
                    float4 v = p[j];
                    a[j].x += v.x; a[j].y += v.y; a[j].z += v.z; a[j].w += v.w;
                }
            }
            const int base_nm = node * AS + 128 + fb;   // nm lives at k in [128,256)
            #pragma unroll
            for (int j = 0; j < 8; j++) {
                put_hl(Ah, Al, base_nm + 4 * j,     a[j].x * 0.0625f, a[j].y * 0.0625f);
                put_hl(Ah, Al, base_nm + 4 * j + 2, a[j].z * 0.0625f, a[j].w * 0.0625f);
            }
            // self x at k in [0,128)
            const float4* p = (const float4*)(x + (size_t)nsrc * FDIM + fb);
            const int base_sf = node * AS + fb;
            #pragma unroll
            for (int j = 0; j < 8; j++) {
                float4 v = p[j];
                put_hl(Ah, Al, base_sf + 4 * j,     v.x, v.y);
                put_hl(Ah, Al, base_sf + 4 * j + 2, v.z, v.w);
            }
        }
    }

    // --- warp-tiled MMA: 8 warps = 4(M) x 2(N64) ; two N-halves of 128 ---
    const int w = tid >> 5, lane = tid & 31;
    const int g = lane >> 2, t = lane & 3;
    const int m0 = (w >> 1) * 32;
    const int n0 = (w & 1) * 64;

    #pragma unroll
    for (int half = 0; half < 2; half++) {
        float acc[2][8][4];
        #pragma unroll
        for (int mi = 0; mi < 2; mi++)
            #pragma unroll
            for (int j = 0; j < 8; j++)
                #pragma unroll
                for (int c = 0; c < 4; c++) acc[mi][j][c] = 0.f;

        for (int kc = 0; kc < 4; kc++) {
            __syncthreads();
            // stage B chunk [128 o][64 k] hi+lo
            #pragma unroll
            for (int r = 0; r < 4; r++) {
                int li = tid + r * 256;       // 0..1023
                int row = li >> 3, kq = (li & 7) * 8;
                size_t src = (size_t)(half * 128 + row) * 256 + kc * 64 + kq;
                *(uint4*)&Bh[row * BS + kq] = *(const uint4*)&g_Bhi[src];
                *(uint4*)&Bl[row * BS + kq] = *(const uint4*)&g_Blo[src];
            }
            __syncthreads();

            #pragma unroll
            for (int kk = 0; kk < 4; kk++) {
                const int ka = kc * 64 + kk * 16;   // absolute k into A
                const int kb = kk * 16;             // local k into B chunk
                uint32_t ah[2][4], al[2][4];
                #pragma unroll
                for (int mi = 0; mi < 2; mi++) {
                    int r0 = m0 + mi * 16 + g;
                    ah[mi][0] = *(const uint32_t*)&Ah[(r0)     * AS + ka + 2 * t];
                    ah[mi][1] = *(const uint32_t*)&Ah[(r0 + 8) * AS + ka + 2 * t];
                    ah[mi][2] = *(const uint32_t*)&Ah[(r0)     * AS + ka + 2 * t + 8];
                    ah[mi][3] = *(const uint32_t*)&Ah[(r0 + 8) * AS + ka + 2 * t + 8];
                    al[mi][0] = *(const uint32_t*)&Al[(r0)     * AS + ka + 2 * t];
                    al[mi][1] = *(const uint32_t*)&Al[(r0 + 8) * AS + ka + 2 * t];
                    al[mi][2] = *(const uint32_t*)&Al[(r0)     * AS + ka + 2 * t + 8];
                    al[mi][3] = *(const uint32_t*)&Al[(r0 + 8) * AS + ka + 2 * t + 8];
                }
                #pragma unroll
                for (int j = 0; j < 8; j++) {
                    int br = (n0 + j * 8 + g) * BS + kb + 2 * t;
                    uint32_t bh0 = *(const uint32_t*)&Bh[br];
                    uint32_t bh1 = *(const uint32_t*)&Bh[br + 8];
                    uint32_t bl0 = *(const uint32_t*)&Bl[br];
                    uint32_t bl1 = *(const uint32_t*)&Bl[br + 8];
                    #pragma unroll
                    for (int mi = 0; mi < 2; mi++) {
                        mma_bf16(acc[mi][j], ah[mi], bh0, bh1);   // hi*hi
                        mma_bf16(acc[mi][j], al[mi], bh0, bh1);   // lo*hi
                        mma_bf16(acc[mi][j], ah[mi], bl0, bl1);   // hi*lo
                    }
                }
            }
        }

        // --- epilogue for this 128-wide output half ---
        #pragma unroll
        for (int mi = 0; mi < 2; mi++) {
            int node0 = nb + m0 + mi * 16 + g;
            int node1 = node0 + 8;
            #pragma unroll
            for (int j = 0; j < 8; j++) {
                int o = half * 128 + n0 + j * 8 + 2 * t;
                float2 bv = *(const float2*)&bias[o];
                if (node0 < N) {
                    float t0 = acc[mi][j][0] + bv.x;
                    float t1 = acc[mi][j][1] + bv.y;
                    float2 v;
                    v.x = (t0 > 0.f) ? t0 : expm1f(t0);
                    v.y = (t1 > 0.f) ? t1 : expm1f(t1);
                    *(float2*)(out + (size_t)node0 * ODIM + o) = v;
                }
                if (node1 < N) {
                    float t2 = acc[mi][j][2] + bv.x;
                    float t3 = acc[mi][j][3] + bv.y;
                    float2 v;
                    v.x = (t2 > 0.f) ? t2 : expm1f(t2);
                    v.y = (t3 > 0.f) ? t3 : expm1f(t3);
                    *(float2*)(out + (size_t)node1 * ODIM + o) = v;
                }
            }
        }
    }
}

// ---------------------------------------------------------------------------
extern "C" void kernel_launch(void* const* d_in, const int* in_sizes, int n_in,
                              void* d_out, int out_size)
{
    const float* x    = (const float*)d_in[0];
    const int*   nbr  = (const int*)  d_in[1];
    const float* R    = (const float*)d_in[2];
    const float* Ws   = (const float*)d_in[3];
    const float* Wn   = (const float*)d_in[4];
    const float* bias = (const float*)d_in[5];
    const int N = in_sizes[0] / FDIM;

    cudaFuncSetAttribute(kB_mma, cudaFuncAttributeMaxDynamicSharedMemorySize, SM_TOT);

    kA<<<dim3(2, 4, 2 * JS), 256>>>(R, Ws, Wn);
    kReduce<<<(2 * FDIM * ODIM) / 256, 256>>>();
    kB_mma<<<(N + 127) / 128, 256, SM_TOT>>>(x, nbr, bias, (float*)d_out, N);
}

// round 4
// speedup vs baseline: 1.7296x; 1.0966x over previous
#include <cuda_runtime.h>
#include <cuda_bf16.h>
#include <math.h>
#include <stdint.h>

// ---------------------------------------------------------------------------
#define FDIM 128
#define DDEG 16
#define KH   2048
#define ODIM 256
#define JS   16
#define JCH  (KH/JS)

// Scratch (device globals; no allocation allowed)
__device__ float g_Mpart[JS][2][FDIM][ODIM];                 // 4 MB partials
__device__ __align__(16) __nv_bfloat16 g_Bhi[ODIM * 256];    // B[o][k] hi
__device__ __align__(16) __nv_bfloat16 g_Blo[ODIM * 256];    // B[o][k] lo

// ---------------------------------------------------------------------------
// Kernel A: partial M[m][f][o] over a 128-wide j chunk (~14us)
// ---------------------------------------------------------------------------
__global__ void __launch_bounds__(256)
kA(const float* __restrict__ R, const float* __restrict__ Ws,
   const float* __restrict__ Wn)
{
    __shared__ float sA[32][68];
    __shared__ float sB[32][68];

    const int ft = blockIdx.x, ot = blockIdx.y, mz = blockIdx.z;
    const int m = mz / JS, jc = mz % JS;
    const float* __restrict__ W = m ? Wn : Ws;
    const int f0 = ft * 64, o0 = ot * 64;
    const int jbase = jc * JCH;
    const int kk = jbase >> 8, hb = jbase & 255;
    const int tid = threadIdx.x, tx = tid & 15, ty = tid >> 4;

    float acc[4][4];
    #pragma unroll
    for (int i = 0; i < 4; i++)
        #pragma unroll
        for (int j = 0; j < 4; j++) acc[i][j] = 0.f;

    for (int jt = 0; jt < JCH; jt += 32) {
        #pragma unroll
        for (int r = 0; r < 2; r++) {
            int li = tid + r * 256;
            int f_l = li >> 3, jj = (li & 7) * 4;
            float4 a4 = *(const float4*)(R + (size_t)kk * (FDIM * 256)
                                           + (size_t)(f0 + f_l) * 256 + hb + jt + jj);
            sA[jj + 0][f_l] = a4.x; sA[jj + 1][f_l] = a4.y;
            sA[jj + 2][f_l] = a4.z; sA[jj + 3][f_l] = a4.w;
        }
        #pragma unroll
        for (int r = 0; r < 2; r++) {
            int li = tid + r * 256;
            int o_l = li >> 3, jj = (li & 7) * 4;
            float4 b4 = *(const float4*)(W + (size_t)(o0 + o_l) * KH + jbase + jt + jj);
            sB[jj + 0][o_l] = b4.x; sB[jj + 1][o_l] = b4.y;
            sB[jj + 2][o_l] = b4.z; sB[jj + 3][o_l] = b4.w;
        }
        __syncthreads();
        #pragma unroll
        for (int jj = 0; jj < 32; jj++) {
            float4 a4 = *(const float4*)&sA[jj][ty * 4];
            float4 b4 = *(const float4*)&sB[jj][tx * 4];
            float a[4] = {a4.x, a4.y, a4.z, a4.w};
            float b[4] = {b4.x, b4.y, b4.z, b4.w};
            #pragma unroll
            for (int i = 0; i < 4; i++)
                #pragma unroll
                for (int j = 0; j < 4; j++) acc[i][j] += a[i] * b[j];
        }
        __syncthreads();
    }
    float* outp = &g_Mpart[jc][m][0][0];
    #pragma unroll
    for (int i = 0; i < 4; i++) {
        float4 v = make_float4(acc[i][0], acc[i][1], acc[i][2], acc[i][3]);
        *(float4*)(outp + (size_t)(f0 + ty * 4 + i) * ODIM + o0 + tx * 4) = v;
    }
}

// Reduce partials, split to bf16 hi/lo, transpose to B[o][k], k = m*128+f.
__global__ void __launch_bounds__(256)
kReduce()
{
    int i = blockIdx.x * 256 + threadIdx.x;  // [m][f][o]
    const float* p = (const float*)g_Mpart;
    float s = 0.f;
    #pragma unroll
    for (int q = 0; q < JS; q++) s += p[(size_t)q * 2 * FDIM * ODIM + i];
    int m = i >> 15, f = (i >> 8) & 127, o = i & 255;
    int k = m * 128 + f;
    __nv_bfloat16 h = __float2bfloat16_rn(s);
    float r = s - __bfloat162float(h);
    g_Bhi[o * 256 + k] = h;
    g_Blo[o * 256 + k] = __float2bfloat16_rn(r);
}

// ---------------------------------------------------------------------------
// kB_mma: 64 nodes/CTA, 128 threads, 2 CTAs/SM. ldmatrix fragment loads.
// ---------------------------------------------------------------------------
#define AS 264   // A smem row stride (bf16) -> 4-bank row offset, conflict-free
#define BS 72    // B smem row stride (bf16)

#define SM_AH 0
#define SM_AL (SM_AH + 64 * AS * 2)        // 33792
#define SM_BH (SM_AL + 64 * AS * 2)        // 67584
#define SM_BL (SM_BH + 128 * BS * 2)       // 86016
#define SM_IX (SM_BL + 128 * BS * 2)       // 104448
#define SM_TOT (SM_IX + 64 * 17 * 4)       // 108800 B -> 2 CTAs/SM

__device__ __forceinline__ uint32_t s2u(const void* p) {
    uint32_t a;
    asm("{ .reg .u64 t; cvta.to.shared.u64 t, %1; cvt.u32.u64 %0, t; }"
        : "=r"(a) : "l"(p));
    return a;
}

#define LDSM4(r, addr) \
    asm volatile("ldmatrix.sync.aligned.m8n8.x4.shared.b16 {%0,%1,%2,%3}, [%4];" \
                 : "=r"((r)[0]), "=r"((r)[1]), "=r"((r)[2]), "=r"((r)[3]) \
                 : "r"(addr))

__device__ __forceinline__ void mma_bf16(float* c, const uint32_t* a,
                                         uint32_t b0, uint32_t b1) {
    asm volatile(
        "mma.sync.aligned.m16n8k16.row.col.f32.bf16.bf16.f32 "
        "{%0,%1,%2,%3}, {%4,%5,%6,%7}, {%8,%9}, {%0,%1,%2,%3};"
        : "+f"(c[0]), "+f"(c[1]), "+f"(c[2]), "+f"(c[3])
        : "r"(a[0]), "r"(a[1]), "r"(a[2]), "r"(a[3]), "r"(b0), "r"(b1));
}

// convert 32 floats (as 8 float4, scaled) into 16 packed hi and 16 packed lo u32
__device__ __forceinline__ void cvt32(const float4* a, float s,
                                      uint32_t* h, uint32_t* l) {
    #pragma unroll
    for (int j = 0; j < 8; j++) {
        float v[4] = {a[j].x * s, a[j].y * s, a[j].z * s, a[j].w * s};
        uint32_t hp[2], lp[2];
        #pragma unroll
        for (int p = 0; p < 2; p++) {
            __nv_bfloat16 h0 = __float2bfloat16_rn(v[2 * p]);
            __nv_bfloat16 h1 = __float2bfloat16_rn(v[2 * p + 1]);
            float r0 = v[2 * p] - __bfloat162float(h0);
            float r1 = v[2 * p + 1] - __bfloat162float(h1);
            hp[p] = ((uint32_t)__bfloat16_as_ushort(h1) << 16) | __bfloat16_as_ushort(h0);
            lp[p] = ((uint32_t)__bfloat16_as_ushort(__float2bfloat16_rn(r1)) << 16)
                  | __bfloat16_as_ushort(__float2bfloat16_rn(r0));
        }
        h[2 * j] = hp[0]; h[2 * j + 1] = hp[1];
        l[2 * j] = lp[0]; l[2 * j + 1] = lp[1];
    }
}

__global__ void __launch_bounds__(128, 2)
kB_mma(const float* __restrict__ x, const int* __restrict__ nbr,
       const float* __restrict__ bias, float* __restrict__ out, int N)
{
    extern __shared__ char smem[];
    __nv_bfloat16* Ah = (__nv_bfloat16*)(smem + SM_AH);
    __nv_bfloat16* Al = (__nv_bfloat16*)(smem + SM_AL);
    __nv_bfloat16* Bh = (__nv_bfloat16*)(smem + SM_BH);
    __nv_bfloat16* Bl = (__nv_bfloat16*)(smem + SM_BL);
    int* sIdx = (int*)(smem + SM_IX);
    const uint32_t sb = s2u(smem);

    const int tid = threadIdx.x;
    const int nb = blockIdx.x * 64;

    // --- neighbor indices ---
    #pragma unroll
    for (int r = 0; r < 8; r++) {
        int li = tid + r * 128;               // 0..1023
        int nl = li >> 4, d = li & 15;
        int src = nb + nl; if (src >= N) src = N - 1;
        sIdx[nl * 17 + d] = nbr[(size_t)src * DDEG + d];
    }
    __syncthreads();

    // --- gather-mean + self -> split-bf16 A in smem (STS.128, conflict-free) ---
    {
        const int node = tid & 63;
        const int q = tid >> 6;               // 64-feat half
        int nsrc = nb + node; if (nsrc >= N) nsrc = N - 1;
        const int* myidx = &sIdx[node * 17];
        uint32_t h[16], l[16];

        #pragma unroll
        for (int blk = 0; blk < 2; blk++) {
            const int fb = q * 64 + blk * 32;
            // neighbor mean over 32 feats
            float4 a[8];
            #pragma unroll
            for (int j = 0; j < 8; j++) a[j] = make_float4(0.f, 0.f, 0.f, 0.f);
            #pragma unroll 2
            for (int d = 0; d < DDEG; d++) {
                const float4* p = (const float4*)(x + (size_t)myidx[d] * FDIM + fb);
                #pragma unroll
                for (int j = 0; j < 8; j++) {
                    float4 v = p[j];
                    a[j].x += v.x; a[j].y += v.y; a[j].z += v.z; a[j].w += v.w;
                }
            }
            cvt32(a, 0.0625f, h, l);           // nm at k in [128,256)
            {
                int base = node * AS + 128 + fb;
                #pragma unroll
                for (int i = 0; i < 4; i++) {
                    *(uint4*)&Ah[base + 8 * i] = *(uint4*)&h[4 * i];
                    *(uint4*)&Al[base + 8 * i] = *(uint4*)&l[4 * i];
                }
            }
            // self x at k in [0,128)
            float4 xv[8];
            const float4* p = (const float4*)(x + (size_t)nsrc * FDIM + fb);
            #pragma unroll
            for (int j = 0; j < 8; j++) xv[j] = p[j];
            cvt32(xv, 1.0f, h, l);
            {
                int base = node * AS + fb;
                #pragma unroll
                for (int i = 0; i < 4; i++) {
                    *(uint4*)&Ah[base + 8 * i] = *(uint4*)&h[4 * i];
                    *(uint4*)&Al[base + 8 * i] = *(uint4*)&l[4 * i];
                }
            }
        }
    }

    // --- warp tiling: 4 warps = 2(M32) x 2(N64); two 128-wide output halves ---
    const int w = tid >> 5, lane = tid & 31;
    const int g = lane >> 2, t = lane & 3;
    const int m0 = (w >> 1) * 32;
    const int n0 = (w & 1) * 64;

    // per-thread ldmatrix byte offsets (within tile, k=0)
    const uint32_t aoff = (uint32_t)(((lane & 15) * AS + ((lane >> 4) << 3)) * 2);
    const uint32_t boff = (uint32_t)((((lane & 7) + ((lane >> 4) << 3)) * BS
                                      + (((lane >> 3) & 1) << 3)) * 2);

    #pragma unroll
    for (int half = 0; half < 2; half++) {
        float acc[2][8][4];
        #pragma unroll
        for (int mi = 0; mi < 2; mi++)
            #pragma unroll
            for (int j = 0; j < 8; j++)
                #pragma unroll
                for (int c = 0; c < 4; c++) acc[mi][j][c] = 0.f;

        for (int kc = 0; kc < 4; kc++) {
            __syncthreads();
            // stage B chunk [128 o][64 k] hi+lo
            #pragma unroll
            for (int r = 0; r < 8; r++) {
                int li = tid + r * 128;        // 0..1023
                int row = li >> 3, kq = (li & 7) * 8;
                size_t src = (size_t)(half * 128 + row) * 256 + kc * 64 + kq;
                *(uint4*)&Bh[row * BS + kq] = *(const uint4*)&g_Bhi[src];
                *(uint4*)&Bl[row * BS + kq] = *(const uint4*)&g_Blo[src];
            }
            __syncthreads();

            #pragma unroll
            for (int kk = 0; kk < 4; kk++) {
                const int ka = kc * 64 + kk * 16;
                const int kb = kk * 16;
                // A fragments via ldmatrix.x4
                uint32_t ah[2][4], al[2][4];
                #pragma unroll
                for (int mi = 0; mi < 2; mi++) {
                    uint32_t base = (uint32_t)(((m0 + mi * 16) * AS + ka) * 2) + aoff;
                    LDSM4(ah[mi], sb + SM_AH + base);
                    LDSM4(al[mi], sb + SM_AL + base);
                }
                // B fragments via ldmatrix.x4 (each covers 2 j's)
                uint32_t bh[8][2], bl[8][2];
                #pragma unroll
                for (int jp = 0; jp < 4; jp++) {
                    uint32_t base = (uint32_t)(((n0 + jp * 16) * BS + kb) * 2) + boff;
                    uint32_t tm[4];
                    LDSM4(tm, sb + SM_BH + base);
                    bh[2 * jp][0] = tm[0]; bh[2 * jp][1] = tm[1];
                    bh[2 * jp + 1][0] = tm[2]; bh[2 * jp + 1][1] = tm[3];
                    LDSM4(tm, sb + SM_BL + base);
                    bl[2 * jp][0] = tm[0]; bl[2 * jp][1] = tm[1];
                    bl[2 * jp + 1][0] = tm[2]; bl[2 * jp + 1][1] = tm[3];
                }
                #pragma unroll
                for (int j = 0; j < 8; j++)
                    #pragma unroll
                    for (int mi = 0; mi < 2; mi++) {
                        mma_bf16(acc[mi][j], ah[mi], bh[j][0], bh[j][1]);  // hi*hi
                        mma_bf16(acc[mi][j], al[mi], bh[j][0], bh[j][1]);  // lo*hi
                        mma_bf16(acc[mi][j], ah[mi], bl[j][0], bl[j][1]);  // hi*lo
                    }
            }
        }

        // --- epilogue for this 128-wide output half ---
        #pragma unroll
        for (int mi = 0; mi < 2; mi++) {
            int node0 = nb + m0 + mi * 16 + g;
            int node1 = node0 + 8;
            #pragma unroll
            for (int j = 0; j < 8; j++) {
                int o = half * 128 + n0 + j * 8 + 2 * t;
                float2 bv = *(const float2*)&bias[o];
                if (node0 < N) {
                    float t0 = acc[mi][j][0] + bv.x;
                    float t1 = acc[mi][j][1] + bv.y;
                    float2 v;
                    v.x = (t0 > 0.f) ? t0 : expm1f(t0);
                    v.y = (t1 > 0.f) ? t1 : expm1f(t1);
                    *(float2*)(out + (size_t)node0 * ODIM + o) = v;
                }
                if (node1 < N) {
                    float t2 = acc[mi][j][2] + bv.x;
                    float t3 = acc[mi][j][3] + bv.y;
                    float2 v;
                    v.x = (t2 > 0.f) ? t2 : expm1f(t2);
                    v.y = (t3 > 0.f) ? t3 : expm1f(t3);
                    *(float2*)(out + (size_t)node1 * ODIM + o) = v;
                }
            }
        }
    }
}

// ---------------------------------------------------------------------------
extern "C" void kernel_launch(void* const* d_in, const int* in_sizes, int n_in,
                              void* d_out, int out_size)
{
    const float* x    = (const float*)d_in[0];
    const int*   nbr  = (const int*)  d_in[1];
    const float* R    = (const float*)d_in[2];
    const float* Ws   = (const float*)d_in[3];
    const float* Wn   = (const float*)d_in[4];
    const float* bias = (const float*)d_in[5];
    const int N = in_sizes[0] / FDIM;

    cudaFuncSetAttribute(kB_mma, cudaFuncAttributeMaxDynamicSharedMemorySize, SM_TOT);

    kA<<<dim3(2, 4, 2 * JS), 256>>>(R, Ws, Wn);
    kReduce<<<(2 * FDIM * ODIM) / 256, 256>>>();
    kB_mma<<<(N + 63) / 64, 128, SM_TOT>>>(x, nbr, bias, (float*)d_out, N);
}

// round 5
// speedup vs baseline: 2.5339x; 1.4650x over previous
#include <cuda_runtime.h>
#include <cuda_bf16.h>
#include <math.h>
#include <stdint.h>

// ---------------------------------------------------------------------------
#define FDIM 128
#define DDEG 16
#define KH   2048
#define ODIM 256
#define JS   16
#define JCH  (KH/JS)

// Scratch (device globals; no allocation allowed)
__device__ float g_Mpart[JS][2][FDIM][ODIM];                 // 4 MB partials
__device__ __align__(16) __nv_bfloat16 g_Bhi[ODIM * 256];    // B[o][k] hi
__device__ __align__(16) __nv_bfloat16 g_Blo[ODIM * 256];    // B[o][k] lo

// ---------------------------------------------------------------------------
// Kernel A: partial M[m][f][o] over a 128-wide j chunk (~14us)
// ---------------------------------------------------------------------------
__global__ void __launch_bounds__(256)
kA(const float* __restrict__ R, const float* __restrict__ Ws,
   const float* __restrict__ Wn)
{
    __shared__ float sA[32][68];
    __shared__ float sB[32][68];

    const int ft = blockIdx.x, ot = blockIdx.y, mz = blockIdx.z;
    const int m = mz / JS, jc = mz % JS;
    const float* __restrict__ W = m ? Wn : Ws;
    const int f0 = ft * 64, o0 = ot * 64;
    const int jbase = jc * JCH;
    const int kk = jbase >> 8, hb = jbase & 255;
    const int tid = threadIdx.x, tx = tid & 15, ty = tid >> 4;

    float acc[4][4];
    #pragma unroll
    for (int i = 0; i < 4; i++)
        #pragma unroll
        for (int j = 0; j < 4; j++) acc[i][j] = 0.f;

    for (int jt = 0; jt < JCH; jt += 32) {
        #pragma unroll
        for (int r = 0; r < 2; r++) {
            int li = tid + r * 256;
            int f_l = li >> 3, jj = (li & 7) * 4;
            float4 a4 = *(const float4*)(R + (size_t)kk * (FDIM * 256)
                                           + (size_t)(f0 + f_l) * 256 + hb + jt + jj);
            sA[jj + 0][f_l] = a4.x; sA[jj + 1][f_l] = a4.y;
            sA[jj + 2][f_l] = a4.z; sA[jj + 3][f_l] = a4.w;
        }
        #pragma unroll
        for (int r = 0; r < 2; r++) {
            int li = tid + r * 256;
            int o_l = li >> 3, jj = (li & 7) * 4;
            float4 b4 = *(const float4*)(W + (size_t)(o0 + o_l) * KH + jbase + jt + jj);
            sB[jj + 0][o_l] = b4.x; sB[jj + 1][o_l] = b4.y;
            sB[jj + 2][o_l] = b4.z; sB[jj + 3][o_l] = b4.w;
        }
        __syncthreads();
        #pragma unroll
        for (int jj = 0; jj < 32; jj++) {
            float4 a4 = *(const float4*)&sA[jj][ty * 4];
            float4 b4 = *(const float4*)&sB[jj][tx * 4];
            float a[4] = {a4.x, a4.y, a4.z, a4.w};
            float b[4] = {b4.x, b4.y, b4.z, b4.w};
            #pragma unroll
            for (int i = 0; i < 4; i++)
                #pragma unroll
                for (int j = 0; j < 4; j++) acc[i][j] += a[i] * b[j];
        }
        __syncthreads();
    }
    float* outp = &g_Mpart[jc][m][0][0];
    #pragma unroll
    for (int i = 0; i < 4; i++) {
        float4 v = make_float4(acc[i][0], acc[i][1], acc[i][2], acc[i][3]);
        *(float4*)(outp + (size_t)(f0 + ty * 4 + i) * ODIM + o0 + tx * 4) = v;
    }
}

// Reduce partials, split to bf16 hi/lo, transpose to B[o][k], k = m*128+f.
__global__ void __launch_bounds__(256)
kReduce()
{
    int i = blockIdx.x * 256 + threadIdx.x;  // [m][f][o]
    const float* p = (const float*)g_Mpart;
    float s = 0.f;
    #pragma unroll
    for (int q = 0; q < JS; q++) s += p[(size_t)q * 2 * FDIM * ODIM + i];
    int m = i >> 15, f = (i >> 8) & 127, o = i & 255;
    int k = m * 128 + f;
    __nv_bfloat16 h = __float2bfloat16_rn(s);
    float r = s - __bfloat162float(h);
    g_Bhi[o * 256 + k] = h;
    g_Blo[o * 256 + k] = __float2bfloat16_rn(r);
}

// ---------------------------------------------------------------------------
// kB_mma: 64 nodes/CTA, 128 threads, 2 CTAs/SM.
//   Gather: warp-cooperative (whole warp loads one row -> 4 lines/LDG).
//   GEMM:   ldmatrix + mma.sync m16n8k16 bf16, 3-pass split-bf16.
// ---------------------------------------------------------------------------
#define AS 264   // A smem row stride (bf16): k=256 + 8 pad, LDSM conflict-free
#define BS 72    // B smem row stride (bf16)

#define SM_AH 0
#define SM_AL (SM_AH + 64 * AS * 2)        // 33792
#define SM_BH (SM_AL + 64 * AS * 2)        // 67584
#define SM_BL (SM_BH + 128 * BS * 2)       // 86016
#define SM_IX (SM_BL + 128 * BS * 2)       // 104448
#define SM_TOT (SM_IX + 64 * 17 * 4)       // 108800 B -> 2 CTAs/SM

__device__ __forceinline__ uint32_t s2u(const void* p) {
    uint32_t a;
    asm("{ .reg .u64 t; cvta.to.shared.u64 t, %1; cvt.u32.u64 %0, t; }"
        : "=r"(a) : "l"(p));
    return a;
}

#define LDSM4(r, addr) \
    asm volatile("ldmatrix.sync.aligned.m8n8.x4.shared.b16 {%0,%1,%2,%3}, [%4];" \
                 : "=r"((r)[0]), "=r"((r)[1]), "=r"((r)[2]), "=r"((r)[3]) \
                 : "r"(addr))

__device__ __forceinline__ void mma_bf16(float* c, const uint32_t* a,
                                         uint32_t b0, uint32_t b1) {
    asm volatile(
        "mma.sync.aligned.m16n8k16.row.col.f32.bf16.bf16.f32 "
        "{%0,%1,%2,%3}, {%4,%5,%6,%7}, {%8,%9}, {%0,%1,%2,%3};"
        : "+f"(c[0]), "+f"(c[1]), "+f"(c[2]), "+f"(c[3])
        : "r"(a[0]), "r"(a[1]), "r"(a[2]), "r"(a[3]), "r"(b0), "r"(b1));
}

// pack 4 scaled floats into split-bf16 hi/lo and store 8B to each array
__device__ __forceinline__ void put4(__nv_bfloat16* Ah, __nv_bfloat16* Al,
                                     int off, float4 v, float s) {
    float f[4] = {v.x * s, v.y * s, v.z * s, v.w * s};
    uint32_t hp[2], lp[2];
    #pragma unroll
    for (int p = 0; p < 2; p++) {
        __nv_bfloat16 h0 = __float2bfloat16_rn(f[2 * p]);
        __nv_bfloat16 h1 = __float2bfloat16_rn(f[2 * p + 1]);
        float r0 = f[2 * p] - __bfloat162float(h0);
        float r1 = f[2 * p + 1] - __bfloat162float(h1);
        hp[p] = ((uint32_t)__bfloat16_as_ushort(h1) << 16) | __bfloat16_as_ushort(h0);
        lp[p] = ((uint32_t)__bfloat16_as_ushort(__float2bfloat16_rn(r1)) << 16)
              | __bfloat16_as_ushort(__float2bfloat16_rn(r0));
    }
    *(uint2*)&Ah[off] = make_uint2(hp[0], hp[1]);
    *(uint2*)&Al[off] = make_uint2(lp[0], lp[1]);
}

__global__ void __launch_bounds__(128, 2)
kB_mma(const float* __restrict__ x, const int* __restrict__ nbr,
       const float* __restrict__ bias, float* __restrict__ out, int N)
{
    extern __shared__ char smem[];
    __nv_bfloat16* Ah = (__nv_bfloat16*)(smem + SM_AH);
    __nv_bfloat16* Al = (__nv_bfloat16*)(smem + SM_AL);
    __nv_bfloat16* Bh = (__nv_bfloat16*)(smem + SM_BH);
    __nv_bfloat16* Bl = (__nv_bfloat16*)(smem + SM_BL);
    int* sIdx = (int*)(smem + SM_IX);
    const uint32_t sb = s2u(smem);

    const int tid = threadIdx.x;
    const int w = tid >> 5, lane = tid & 31;
    const int nb = blockIdx.x * 64;

    // --- neighbor indices ---
    #pragma unroll
    for (int r = 0; r < 8; r++) {
        int li = tid + r * 128;               // 0..1023
        int nl = li >> 4, d = li & 15;
        int src = nb + nl; if (src >= N) src = N - 1;
        sIdx[nl * 17 + d] = nbr[(size_t)src * DDEG + d];
    }
    __syncthreads();

    // --- warp-cooperative gather-mean + self -> split-bf16 A ---
    // warp w handles nodes [w*16, w*16+16); all 32 lanes read the SAME row,
    // lane l takes feats [4l, 4l+4) -> each LDG.128 touches only 4 lines.
    {
        #pragma unroll 2
        for (int i = 0; i < 16; i++) {
            const int node = w * 16 + i;
            const int* myidx = &sIdx[node * 17];
            int nsrc = nb + node; if (nsrc >= N) nsrc = N - 1;

            float4 a = make_float4(0.f, 0.f, 0.f, 0.f);
            #pragma unroll
            for (int d = 0; d < DDEG; d++) {
                float4 v = *(const float4*)(x + (size_t)myidx[d] * FDIM + lane * 4);
                a.x += v.x; a.y += v.y; a.z += v.z; a.w += v.w;
            }
            float4 sv = *(const float4*)(x + (size_t)nsrc * FDIM + lane * 4);

            put4(Ah, Al, node * AS + 128 + lane * 4, a, 0.0625f);  // nm: k in [128,256)
            put4(Ah, Al, node * AS + lane * 4, sv, 1.0f);          // self: k in [0,128)
        }
    }

    // --- warp tiling: 4 warps = 2(M32) x 2(N64); two 128-wide output halves ---
    const int g = lane >> 2, t = lane & 3;
    const int m0 = (w >> 1) * 32;
    const int n0 = (w & 1) * 64;

    // per-thread ldmatrix byte offsets (within tile, k=0)
    const uint32_t aoff = (uint32_t)(((lane & 15) * AS + ((lane >> 4) << 3)) * 2);
    const uint32_t boff = (uint32_t)((((lane & 7) + ((lane >> 4) << 3)) * BS
                                      + (((lane >> 3) & 1) << 3)) * 2);

    #pragma unroll
    for (int half = 0; half < 2; half++) {
        float acc[2][8][4];
        #pragma unroll
        for (int mi = 0; mi < 2; mi++)
            #pragma unroll
            for (int j = 0; j < 8; j++)
                #pragma unroll
                for (int c = 0; c < 4; c++) acc[mi][j][c] = 0.f;

        for (int kc = 0; kc < 4; kc++) {
            __syncthreads();
            // stage B chunk [128 o][64 k] hi+lo
            #pragma unroll
            for (int r = 0; r < 8; r++) {
                int li = tid + r * 128;        // 0..1023
                int row = li >> 3, kq = (li & 7) * 8;
                size_t src = (size_t)(half * 128 + row) * 256 + kc * 64 + kq;
                *(uint4*)&Bh[row * BS + kq] = *(const uint4*)&g_Bhi[src];
                *(uint4*)&Bl[row * BS + kq] = *(const uint4*)&g_Blo[src];
            }
            __syncthreads();

            #pragma unroll
            for (int kk = 0; kk < 4; kk++) {
                const int ka = kc * 64 + kk * 16;
                const int kb = kk * 16;
                // A fragments via ldmatrix.x4
                uint32_t ah[2][4], al[2][4];
                #pragma unroll
                for (int mi = 0; mi < 2; mi++) {
                    uint32_t base = (uint32_t)(((m0 + mi * 16) * AS + ka) * 2) + aoff;
                    LDSM4(ah[mi], sb + SM_AH + base);
                    LDSM4(al[mi], sb + SM_AL + base);
                }
                // B fragments via ldmatrix.x4 (each covers 2 j's)
                uint32_t bh[8][2], bl[8][2];
                #pragma unroll
                for (int jp = 0; jp < 4; jp++) {
                    uint32_t base = (uint32_t)(((n0 + jp * 16) * BS + kb) * 2) + boff;
                    uint32_t tm[4];
                    LDSM4(tm, sb + SM_BH + base);
                    bh[2 * jp][0] = tm[0]; bh[2 * jp][1] = tm[1];
                    bh[2 * jp + 1][0] = tm[2]; bh[2 * jp + 1][1] = tm[3];
                    LDSM4(tm, sb + SM_BL + base);
                    bl[2 * jp][0] = tm[0]; bl[2 * jp][1] = tm[1];
                    bl[2 * jp + 1][0] = tm[2]; bl[2 * jp + 1][1] = tm[3];
                }
                #pragma unroll
                for (int j = 0; j < 8; j++)
                    #pragma unroll
                    for (int mi = 0; mi < 2; mi++) {
                        mma_bf16(acc[mi][j], ah[mi], bh[j][0], bh[j][1]);  // hi*hi
                        mma_bf16(acc[mi][j], al[mi], bh[j][0], bh[j][1]);  // lo*hi
                        mma_bf16(acc[mi][j], ah[mi], bl[j][0], bl[j][1]);  // hi*lo
                    }
            }
        }

        // --- epilogue for this 128-wide output half ---
        #pragma unroll
        for (int mi = 0; mi < 2; mi++) {
            int node0 = nb + m0 + mi * 16 + g;
            int node1 = node0 + 8;
            #pragma unroll
            for (int j = 0; j < 8; j++) {
                int o = half * 128 + n0 + j * 8 + 2 * t;
                float2 bv = *(const float2*)&bias[o];
                if (node0 < N) {
                    float t0 = acc[mi][j][0] + bv.x;
                    float t1 = acc[mi][j][1] + bv.y;
                    float2 v;
                    v.x = (t0 > 0.f) ? t0 : expm1f(t0);
                    v.y = (t1 > 0.f) ? t1 : expm1f(t1);
                    *(float2*)(out + (size_t)node0 * ODIM + o) = v;
                }
                if (node1 < N) {
                    float t2 = acc[mi][j][2] + bv.x;
                    float t3 = acc[mi][j][3] + bv.y;
                    float2 v;
                    v.x = (t2 > 0.f) ? t2 : expm1f(t2);
                    v.y = (t3 > 0.f) ? t3 : expm1f(t3);
                    *(float2*)(out + (size_t)node1 * ODIM + o) = v;
                }
            }
        }
    }
}

// ---------------------------------------------------------------------------
extern "C" void kernel_launch(void* const* d_in, const int* in_sizes, int n_in,
                              void* d_out, int out_size)
{
    const float* x    = (const float*)d_in[0];
    const int*   nbr  = (const int*)  d_in[1];
    const float* R    = (const float*)d_in[2];
    const float* Ws   = (const float*)d_in[3];
    const float* Wn   = (const float*)d_in[4];
    const float* bias = (const float*)d_in[5];
    const int N = in_sizes[0] / FDIM;

    cudaFuncSetAttribute(kB_mma, cudaFuncAttributeMaxDynamicSharedMemorySize, SM_TOT);

    kA<<<dim3(2, 4, 2 * JS), 256>>>(R, Ws, Wn);
    kReduce<<<(2 * FDIM * ODIM) / 256, 256>>>();
    kB_mma<<<(N + 63) / 64, 128, SM_TOT>>>(x, nbr, bias, (float*)d_out, N);
}

// round 6
// speedup vs baseline: 2.9815x; 1.1766x over previous
#include <cuda_runtime.h>
#include <cuda_bf16.h>
#include <math.h>
#include <stdint.h>

// ---------------------------------------------------------------------------
#define FDIM 128
#define DDEG 16
#define KH   2048
#define ODIM 256
#define JS   16
#define JCH  (KH/JS)

// Scratch (device globals; no allocation allowed)
__device__ float g_Mpart[JS][2][FDIM][ODIM];                 // 4 MB partials
__device__ __align__(16) __nv_bfloat16 g_Bhi[ODIM * 256];    // B[o][k] hi
__device__ __align__(16) __nv_bfloat16 g_Blo[ODIM * 256];    // B[o][k] lo

// ---------------------------------------------------------------------------
// Kernel A: partial M[m][f][o] over a 128-wide j chunk (~14us)
// ---------------------------------------------------------------------------
__global__ void __launch_bounds__(256)
kA(const float* __restrict__ R, const float* __restrict__ Ws,
   const float* __restrict__ Wn)
{
    __shared__ float sA[32][68];
    __shared__ float sB[32][68];

    const int ft = blockIdx.x, ot = blockIdx.y, mz = blockIdx.z;
    const int m = mz / JS, jc = mz % JS;
    const float* __restrict__ W = m ? Wn : Ws;
    const int f0 = ft * 64, o0 = ot * 64;
    const int jbase = jc * JCH;
    const int kk = jbase >> 8, hb = jbase & 255;
    const int tid = threadIdx.x, tx = tid & 15, ty = tid >> 4;

    float acc[4][4];
    #pragma unroll
    for (int i = 0; i < 4; i++)
        #pragma unroll
        for (int j = 0; j < 4; j++) acc[i][j] = 0.f;

    for (int jt = 0; jt < JCH; jt += 32) {
        #pragma unroll
        for (int r = 0; r < 2; r++) {
            int li = tid + r * 256;
            int f_l = li >> 3, jj = (li & 7) * 4;
            float4 a4 = *(const float4*)(R + (size_t)kk * (FDIM * 256)
                                           + (size_t)(f0 + f_l) * 256 + hb + jt + jj);
            sA[jj + 0][f_l] = a4.x; sA[jj + 1][f_l] = a4.y;
            sA[jj + 2][f_l] = a4.z; sA[jj + 3][f_l] = a4.w;
        }
        #pragma unroll
        for (int r = 0; r < 2; r++) {
            int li = tid + r * 256;
            int o_l = li >> 3, jj = (li & 7) * 4;
            float4 b4 = *(const float4*)(W + (size_t)(o0 + o_l) * KH + jbase + jt + jj);
            sB[jj + 0][o_l] = b4.x; sB[jj + 1][o_l] = b4.y;
            sB[jj + 2][o_l] = b4.z; sB[jj + 3][o_l] = b4.w;
        }
        __syncthreads();
        #pragma unroll
        for (int jj = 0; jj < 32; jj++) {
            float4 a4 = *(const float4*)&sA[jj][ty * 4];
            float4 b4 = *(const float4*)&sB[jj][tx * 4];
            float a[4] = {a4.x, a4.y, a4.z, a4.w};
            float b[4] = {b4.x, b4.y, b4.z, b4.w};
            #pragma unroll
            for (int i = 0; i < 4; i++)
                #pragma unroll
                for (int j = 0; j < 4; j++) acc[i][j] += a[i] * b[j];
        }
        __syncthreads();
    }
    float* outp = &g_Mpart[jc][m][0][0];
    #pragma unroll
    for (int i = 0; i < 4; i++) {
        float4 v = make_float4(acc[i][0], acc[i][1], acc[i][2], acc[i][3]);
        *(float4*)(outp + (size_t)(f0 + ty * 4 + i) * ODIM + o0 + tx * 4) = v;
    }
}

// Reduce partials, split to bf16 hi/lo, transpose to B[o][k], k = m*128+f.
__global__ void __launch_bounds__(256)
kReduce()
{
    int i = blockIdx.x * 256 + threadIdx.x;  // [m][f][o]
    const float* p = (const float*)g_Mpart;
    float s = 0.f;
    #pragma unroll
    for (int q = 0; q < JS; q++) s += p[(size_t)q * 2 * FDIM * ODIM + i];
    int m = i >> 15, f = (i >> 8) & 127, o = i & 255;
    int k = m * 128 + f;
    __nv_bfloat16 h = __float2bfloat16_rn(s);
    float r = s - __bfloat162float(h);
    g_Bhi[o * 256 + k] = h;
    g_Blo[o * 256 + k] = __float2bfloat16_rn(r);
}

// ---------------------------------------------------------------------------
// kB_mma: 64 nodes/CTA, 128 threads, 2 CTAs/SM.
//   Gather: warp-cooperative (4 lines/LDG).
//   B:      cp.async double-buffered 32-k chunks (L2 latency hidden).
//   GEMM:   ldmatrix + mma.sync m16n8k16 bf16, 3-pass split-bf16.
// ---------------------------------------------------------------------------
#define AS 264   // A smem row stride (bf16): conflict-free LDSM
#define BS2 40   // B chunk smem row stride (bf16): conflict-free LDSM

#define SM_AH 0
#define SM_AL (SM_AH + 64 * AS * 2)            // 33792
#define SM_BB (SM_AL + 64 * AS * 2)            // 67584: 4 x (128*BS2*2 = 10240)
#define SM_IX (SM_BB + 4 * 128 * BS2 * 2)      // 108544
#define SM_TOT (SM_IX + 64 * 17 * 4)           // 112896 B -> 2 CTAs/SM

#define BBUF(b, a) (SM_BB + ((b) * 2 + (a)) * (128 * BS2 * 2))

__device__ __forceinline__ uint32_t s2u(const void* p) {
    uint32_t a;
    asm("{ .reg .u64 t; cvta.to.shared.u64 t, %1; cvt.u32.u64 %0, t; }"
        : "=r"(a) : "l"(p));
    return a;
}

#define CP16(s, g) \
    asm volatile("cp.async.cg.shared.global [%0], [%1], 16;" :: "r"(s), "l"(g))
#define CP_COMMIT() asm volatile("cp.async.commit_group;" ::: "memory")
#define CP_WAIT1()  asm volatile("cp.async.wait_group 1;" ::: "memory")
#define CP_WAIT0()  asm volatile("cp.async.wait_group 0;" ::: "memory")

#define LDSM4(r, addr) \
    asm volatile("ldmatrix.sync.aligned.m8n8.x4.shared.b16 {%0,%1,%2,%3}, [%4];" \
                 : "=r"((r)[0]), "=r"((r)[1]), "=r"((r)[2]), "=r"((r)[3]) \
                 : "r"(addr))

__device__ __forceinline__ void mma_bf16(float* c, const uint32_t* a,
                                         uint32_t b0, uint32_t b1) {
    asm volatile(
        "mma.sync.aligned.m16n8k16.row.col.f32.bf16.bf16.f32 "
        "{%0,%1,%2,%3}, {%4,%5,%6,%7}, {%8,%9}, {%0,%1,%2,%3};"
        : "+f"(c[0]), "+f"(c[1]), "+f"(c[2]), "+f"(c[3])
        : "r"(a[0]), "r"(a[1]), "r"(a[2]), "r"(a[3]), "r"(b0), "r"(b1));
}

// pack 4 scaled floats into split-bf16 hi/lo and store 8B to each array
__device__ __forceinline__ void put4(__nv_bfloat16* Ah, __nv_bfloat16* Al,
                                     int off, float4 v, float s) {
    float f[4] = {v.x * s, v.y * s, v.z * s, v.w * s};
    uint32_t hp[2], lp[2];
    #pragma unroll
    for (int p = 0; p < 2; p++) {
        __nv_bfloat16 h0 = __float2bfloat16_rn(f[2 * p]);
        __nv_bfloat16 h1 = __float2bfloat16_rn(f[2 * p + 1]);
        float r0 = f[2 * p] - __bfloat162float(h0);
        float r1 = f[2 * p + 1] - __bfloat162float(h1);
        hp[p] = ((uint32_t)__bfloat16_as_ushort(h1) << 16) | __bfloat16_as_ushort(h0);
        lp[p] = ((uint32_t)__bfloat16_as_ushort(__float2bfloat16_rn(r1)) << 16)
              | __bfloat16_as_ushort(__float2bfloat16_rn(r0));
    }
    *(uint2*)&Ah[off] = make_uint2(hp[0], hp[1]);
    *(uint2*)&Al[off] = make_uint2(lp[0], lp[1]);
}

// async-stage one 32-k B chunk (hi+lo) into buffer b
__device__ __forceinline__ void stageB(uint32_t sb, int b, int half, int kc, int tid) {
    const uint32_t dh = sb + BBUF(b, 0);
    const uint32_t dl = sb + BBUF(b, 1);
    #pragma unroll
    for (int r = 0; r < 4; r++) {
        int li = tid + r * 128;          // 0..511
        int row = li >> 2, seg = li & 3;
        size_t gsrc = (size_t)(half * 128 + row) * 256 + kc * 32 + seg * 8;
        uint32_t sa = (uint32_t)(row * (BS2 * 2) + seg * 16);
        CP16(dh + sa, (const char*)&g_Bhi[gsrc]);
        CP16(dl + sa, (const char*)&g_Blo[gsrc]);
    }
}

__global__ void __launch_bounds__(128, 2)
kB_mma(const float* __restrict__ x, const int* __restrict__ nbr,
       const float* __restrict__ bias, float* __restrict__ out, int N)
{
    extern __shared__ char smem[];
    __nv_bfloat16* Ah = (__nv_bfloat16*)(smem + SM_AH);
    __nv_bfloat16* Al = (__nv_bfloat16*)(smem + SM_AL);
    int* sIdx = (int*)(smem + SM_IX);
    const uint32_t sb = s2u(smem);

    const int tid = threadIdx.x;
    const int w = tid >> 5, lane = tid & 31;
    const int nb = blockIdx.x * 64;

    // kick off B chunk 0 immediately (hidden under the whole gather)
    stageB(sb, 0, 0, 0, tid);
    CP_COMMIT();

    // --- neighbor indices ---
    #pragma unroll
    for (int r = 0; r < 8; r++) {
        int li = tid + r * 128;               // 0..1023
        int nl = li >> 4, d = li & 15;
        int src = nb + nl; if (src >= N) src = N - 1;
        sIdx[nl * 17 + d] = nbr[(size_t)src * DDEG + d];
    }
    __syncthreads();

    // --- warp-cooperative gather-mean + self -> split-bf16 A ---
    {
        #pragma unroll 2
        for (int i = 0; i < 16; i++) {
            const int node = w * 16 + i;
            const int* myidx = &sIdx[node * 17];
            int nsrc = nb + node; if (nsrc >= N) nsrc = N - 1;

            float4 a = make_float4(0.f, 0.f, 0.f, 0.f);
            #pragma unroll
            for (int d = 0; d < DDEG; d++) {
                float4 v = *(const float4*)(x + (size_t)myidx[d] * FDIM + lane * 4);
                a.x += v.x; a.y += v.y; a.z += v.z; a.w += v.w;
            }
            float4 sv = *(const float4*)(x + (size_t)nsrc * FDIM + lane * 4);

            put4(Ah, Al, node * AS + 128 + lane * 4, a, 0.0625f);  // nm: k in [128,256)
            put4(Ah, Al, node * AS + lane * 4, sv, 1.0f);          // self: k in [0,128)
        }
    }

    // --- warp tiling: 4 warps = 2(M32) x 2(N64); two 128-wide output halves ---
    const int g = lane >> 2, t = lane & 3;
    const int m0 = (w >> 1) * 32;
    const int n0 = (w & 1) * 64;

    const uint32_t aoff = (uint32_t)(((lane & 15) * AS + ((lane >> 4) << 3)) * 2);
    const uint32_t boff = (uint32_t)((((lane & 7) + ((lane >> 4) << 3)) * BS2
                                      + (((lane >> 3) & 1) << 3)) * 2);

    #pragma unroll
    for (int half = 0; half < 2; half++) {
        float acc[2][8][4];
        #pragma unroll
        for (int mi = 0; mi < 2; mi++)
            #pragma unroll
            for (int j = 0; j < 8; j++)
                #pragma unroll
                for (int c = 0; c < 4; c++) acc[mi][j][c] = 0.f;

        for (int kc = 0; kc < 8; kc++) {
            const int cc = half * 8 + kc;
            if (cc < 15) {
                const int nc = cc + 1;
                stageB(sb, nc & 1, nc >> 3, nc & 7, tid);
                CP_COMMIT();
                CP_WAIT1();              // chunk cc now resident
            } else {
                CP_WAIT0();
            }
            __syncthreads();

            const uint32_t bhB = sb + BBUF(cc & 1, 0);
            const uint32_t blB = sb + BBUF(cc & 1, 1);

            #pragma unroll
            for (int kk = 0; kk < 2; kk++) {
                const int ka = kc * 32 + kk * 16;
                // A fragments
                uint32_t ah[2][4], al[2][4];
                #pragma unroll
                for (int mi = 0; mi < 2; mi++) {
                    uint32_t base = (uint32_t)(((m0 + mi * 16) * AS + ka) * 2) + aoff;
                    LDSM4(ah[mi], sb + SM_AH + base);
                    LDSM4(al[mi], sb + SM_AL + base);
                }
                // B fragments (each x4 covers 2 j's)
                uint32_t bh[8][2], bl[8][2];
                #pragma unroll
                for (int jp = 0; jp < 4; jp++) {
                    uint32_t base = (uint32_t)(((n0 + jp * 16) * BS2 + kk * 16) * 2) + boff;
                    uint32_t tm[4];
                    LDSM4(tm, bhB + base);
                    bh[2 * jp][0] = tm[0]; bh[2 * jp][1] = tm[1];
                    bh[2 * jp + 1][0] = tm[2]; bh[2 * jp + 1][1] = tm[3];
                    LDSM4(tm, blB + base);
                    bl[2 * jp][0] = tm[0]; bl[2 * jp][1] = tm[1];
                    bl[2 * jp + 1][0] = tm[2]; bl[2 * jp + 1][1] = tm[3];
                }
                #pragma unroll
                for (int j = 0; j < 8; j++)
                    #pragma unroll
                    for (int mi = 0; mi < 2; mi++) {
                        mma_bf16(acc[mi][j], ah[mi], bh[j][0], bh[j][1]);  // hi*hi
                        mma_bf16(acc[mi][j], al[mi], bh[j][0], bh[j][1]);  // lo*hi
                        mma_bf16(acc[mi][j], ah[mi], bl[j][0], bl[j][1]);  // hi*lo
                    }
            }
            __syncthreads();
        }

        // --- epilogue for this 128-wide output half (fast ELU) ---
        #pragma unroll
        for (int mi = 0; mi < 2; mi++) {
            int node0 = nb + m0 + mi * 16 + g;
            int node1 = node0 + 8;
            #pragma unroll
            for (int j = 0; j < 8; j++) {
                int o = half * 128 + n0 + j * 8 + 2 * t;
                float2 bv = *(const float2*)&bias[o];
                if (node0 < N) {
                    float t0 = acc[mi][j][0] + bv.x;
                    float t1 = acc[mi][j][1] + bv.y;
                    float2 v;
                    v.x = (t0 > 0.f) ? t0 : (__expf(t0) - 1.0f);
                    v.y = (t1 > 0.f) ? t1 : (__expf(t1) - 1.0f);
                    *(float2*)(out + (size_t)node0 * ODIM + o) = v;
                }
                if (node1 < N) {
                    float t2 = acc[mi][j][2] + bv.x;
                    float t3 = acc[mi][j][3] + bv.y;
                    float2 v;
                    v.x = (t2 > 0.f) ? t2 : (__expf(t2) - 1.0f);
                    v.y = (t3 > 0.f) ? t3 : (__expf(t3) - 1.0f);
                    *(float2*)(out + (size_t)node1 * ODIM + o) = v;
                }
            }
        }
    }
}

// ---------------------------------------------------------------------------
extern "C" void kernel_launch(void* const* d_in, const int* in_sizes, int n_in,
                              void* d_out, int out_size)
{
    const float* x    = (const float*)d_in[0];
    const int*   nbr  = (const int*)  d_in[1];
    const float* R    = (const float*)d_in[2];
    const float* Ws   = (const float*)d_in[3];
    const float* Wn   = (const float*)d_in[4];
    const float* bias = (const float*)d_in[5];
    const int N = in_sizes[0] / FDIM;

    cudaFuncSetAttribute(kB_mma, cudaFuncAttributeMaxDynamicSharedMemorySize, SM_TOT);

    kA<<<dim3(2, 4, 2 * JS), 256>>>(R, Ws, Wn);
    kReduce<<<(2 * FDIM * ODIM) / 256, 256>>>();
    kB_mma<<<(N + 63) / 64, 128, SM_TOT>>>(x, nbr, bias, (float*)d_out, N);
}